// round 2
// baseline (speedup 1.0000x reference)
#include <cuda_runtime.h>

#define NN 100000
#define D_IN 128
#define D_HID 128
#define D_OUT 64

// ---------------- scratch (device globals; no allocation allowed) ----------------
__device__ float g_deg[NN];
__device__ float g_dinv[NN];
__device__ float g_xw1[(long long)NN * D_HID];   // x @ W1
__device__ float g_agg1[(long long)NN * D_HID];  // scatter-add result layer 1
__device__ float g_xw2[(long long)NN * D_OUT];   // relu(h) @ W2
__device__ float g_agg2[(long long)NN * D_OUT];  // scatter-add result layer 2
__device__ int   g_idx64;                        // 1 if edge_index is int64, else int32

__device__ __forceinline__ long long ld_idx(const void* p, long long i, int is64) {
    if (is64) return ((const long long*)p)[i];
    return (long long)((const int*)p)[i];
}

// ---------------- kernel 0: zero scratch + sniff index dtype ----------------
__global__ void k_zero(const void* ei) {
    long long i = (long long)blockIdx.x * blockDim.x + threadIdx.x;
    long long stride = (long long)gridDim.x * blockDim.x;
    const long long n1 = (long long)NN * D_HID;
    const long long n2 = (long long)NN * D_OUT;
    for (long long j = i; j < n1; j += stride) g_agg1[j] = 0.0f;
    for (long long j = i; j < n2; j += stride) g_agg2[j] = 0.0f;
    for (long long j = i; j < NN; j += stride) g_deg[j] = 0.0f;
    if (blockIdx.x == 0 && threadIdx.x == 0) {
        // int64 little-endian nonneg values < 2^31 => every odd 32-bit word is 0.
        // For int32 data the odd words are random node ids; P(16 of them all
        // zero) ~ (1e-5)^16 ~ 0. Reads stay within first 128 bytes (in bounds
        // for either dtype at E=1.6M).
        const unsigned* w = (const unsigned*)ei;
        int all0 = 1;
        for (int k = 1; k < 32; k += 2) all0 &= (w[k] == 0u);
        g_idx64 = all0;
    }
}

// ---------------- kernel 1: degree of target nodes (col) ----------------
__global__ void k_deg(const void* ei, long long E) {
    int is64 = g_idx64;
    long long e = (long long)blockIdx.x * blockDim.x + threadIdx.x;
    if (e >= E) return;
    long long c = ld_idx(ei, E + e, is64);
    float* p = &g_deg[c];
    asm volatile("red.global.add.f32 [%0], %1;" :: "l"(p), "f"(1.0f) : "memory");
}

// ---------------- kernel 2: dinv = deg>0 ? rsqrt(deg) : 0 ----------------
__global__ void k_dinv() {
    int i = blockIdx.x * blockDim.x + threadIdx.x;
    if (i >= NN) return;
    float d = g_deg[i];
    g_dinv[i] = (d > 0.0f) ? rsqrtf(d) : 0.0f;
}

// ---------------- tiled SGEMM: C[M,N] = op(A)[M,K] @ B[K,N] ----------------
// op(A) = relu(A + bias) if relu != 0 (bias broadcast over K dim), else A.
// BM=64, BN=64, BK=16, TM=TN=4, 256 threads.
__global__ __launch_bounds__(256) void k_gemm(
    const float* __restrict__ A, const float* __restrict__ B,
    const float* __restrict__ bias, float* __restrict__ C,
    int M, int N, int K, int relu)
{
    __shared__ float As[16][68];  // [k][m], padded row keeps conflicts low
    __shared__ float Bs[16][64];  // [k][n]

    const int tid = threadIdx.x;
    const int tx = tid & 15;        // col group
    const int ty = tid >> 4;        // row group
    const int m0 = blockIdx.x * 64;
    const int n0 = blockIdx.y * 64;

    float acc[4][4] = {};

    for (int kt = 0; kt < K; kt += 16) {
        // --- load A tile (transposed into As[k][m]) ---
        {
            int am = tid >> 2;            // 0..63
            int ak = (tid & 3) * 4;       // 0,4,8,12
            float4 av = make_float4(0.f, 0.f, 0.f, 0.f);
            int gm = m0 + am;
            if (gm < M) {
                av = *(const float4*)(A + (long long)gm * K + kt + ak);
                if (relu) {
                    const float* bp = bias + kt + ak;
                    av.x = fmaxf(av.x + bp[0], 0.f);
                    av.y = fmaxf(av.y + bp[1], 0.f);
                    av.z = fmaxf(av.z + bp[2], 0.f);
                    av.w = fmaxf(av.w + bp[3], 0.f);
                }
            }
            As[ak + 0][am] = av.x;
            As[ak + 1][am] = av.y;
            As[ak + 2][am] = av.z;
            As[ak + 3][am] = av.w;
        }
        // --- load B tile ---
        {
            int bk = tid >> 4;            // 0..15
            int bc = (tid & 15) * 4;      // 0..60
            *(float4*)&Bs[bk][bc] = *(const float4*)(B + (long long)(kt + bk) * N + n0 + bc);
        }
        __syncthreads();

        #pragma unroll
        for (int kk = 0; kk < 16; kk++) {
            float4 a = *(const float4*)&As[kk][ty * 4];
            float4 b = *(const float4*)&Bs[kk][tx * 4];
            acc[0][0] += a.x * b.x; acc[0][1] += a.x * b.y; acc[0][2] += a.x * b.z; acc[0][3] += a.x * b.w;
            acc[1][0] += a.y * b.x; acc[1][1] += a.y * b.y; acc[1][2] += a.y * b.z; acc[1][3] += a.y * b.w;
            acc[2][0] += a.z * b.x; acc[2][1] += a.z * b.y; acc[2][2] += a.z * b.z; acc[2][3] += a.z * b.w;
            acc[3][0] += a.w * b.x; acc[3][1] += a.w * b.y; acc[3][2] += a.w * b.z; acc[3][3] += a.w * b.w;
        }
        __syncthreads();
    }

    #pragma unroll
    for (int i = 0; i < 4; i++) {
        int gm = m0 + ty * 4 + i;
        if (gm < M) {
            float4 v = make_float4(acc[i][0], acc[i][1], acc[i][2], acc[i][3]);
            *(float4*)(C + (long long)gm * N + n0 + tx * 4) = v;
        }
    }
}

// ---------------- kernel: layer-1 scatter (warp per edge, 128 floats) ----------------
__global__ void k_scatter1(const void* ei, long long E) {
    int is64 = g_idx64;
    long long warp = (long long)blockIdx.x * (blockDim.x >> 5) + (threadIdx.x >> 5);
    int lane = threadIdx.x & 31;
    if (warp >= E) return;
    long long r = ld_idx(ei, warp, is64);
    long long c = ld_idx(ei, E + warp, is64);
    float nrm = g_dinv[r] * g_dinv[c];
    float4 v = *((const float4*)(g_xw1 + r * D_HID) + lane);
    v.x *= nrm; v.y *= nrm; v.z *= nrm; v.w *= nrm;
    float* dst = g_agg1 + c * D_HID + lane * 4;
    asm volatile("red.global.add.v4.f32 [%0], {%1, %2, %3, %4};"
                 :: "l"(dst), "f"(v.x), "f"(v.y), "f"(v.z), "f"(v.w) : "memory");
}

// ---------------- kernel: layer-2 scatter (half-warp per edge, 64 floats) ----------------
__global__ void k_scatter2(const void* ei, long long E) {
    int is64 = g_idx64;
    long long hw = (long long)blockIdx.x * (blockDim.x >> 4) + (threadIdx.x >> 4);
    int lane = threadIdx.x & 15;
    if (hw >= E) return;
    long long r = ld_idx(ei, hw, is64);
    long long c = ld_idx(ei, E + hw, is64);
    float nrm = g_dinv[r] * g_dinv[c];
    float4 v = *((const float4*)(g_xw2 + r * D_OUT) + lane);
    v.x *= nrm; v.y *= nrm; v.z *= nrm; v.w *= nrm;
    float* dst = g_agg2 + c * D_OUT + lane * 4;
    asm volatile("red.global.add.v4.f32 [%0], {%1, %2, %3, %4};"
                 :: "l"(dst), "f"(v.x), "f"(v.y), "f"(v.z), "f"(v.w) : "memory");
}

// ---------------- kernel: edge score = sigmoid(dot(h2[row], h2[col])) ----------------
__global__ void k_score(const void* ei, long long E, const float* __restrict__ b2,
                        float* __restrict__ out) {
    int is64 = g_idx64;
    long long warp = (long long)blockIdx.x * (blockDim.x >> 5) + (threadIdx.x >> 5);
    int lane = threadIdx.x & 31;
    if (warp >= E) return;
    long long r = ld_idx(ei, warp, is64);
    long long c = ld_idx(ei, E + warp, is64);
    float2 bv = *(const float2*)(b2 + lane * 2);
    float2 hr = *(const float2*)(g_agg2 + r * D_OUT + lane * 2);
    float2 hc = *(const float2*)(g_agg2 + c * D_OUT + lane * 2);
    hr.x += bv.x; hr.y += bv.y;
    hc.x += bv.x; hc.y += bv.y;
    float s = hr.x * hc.x + hr.y * hc.y;
    #pragma unroll
    for (int o = 16; o > 0; o >>= 1) s += __shfl_xor_sync(0xFFFFFFFF, s, o);
    if (lane == 0) out[warp] = 1.0f / (1.0f + __expf(-s));
}

// ---------------- launch ----------------
extern "C" void kernel_launch(void* const* d_in, const int* in_sizes, int n_in,
                              void* d_out, int out_size) {
    const float* x  = (const float*)d_in[0];
    const void*  ei = d_in[1];
    const float* W1 = (const float*)d_in[2];
    const float* b1 = (const float*)d_in[3];
    const float* W2 = (const float*)d_in[4];
    const float* b2 = (const float*)d_in[5];
    float* out = (float*)d_out;
    long long E = (long long)in_sizes[1] / 2;

    float *p_xw1, *p_agg1, *p_xw2;
    cudaGetSymbolAddress((void**)&p_xw1,  g_xw1);
    cudaGetSymbolAddress((void**)&p_agg1, g_agg1);
    cudaGetSymbolAddress((void**)&p_xw2,  g_xw2);

    k_zero<<<2048, 256>>>(ei);
    k_deg<<<(int)((E + 255) / 256), 256>>>(ei, E);
    k_dinv<<<(NN + 255) / 256, 256>>>();

    // xw1 = x @ W1    (M=NN, N=128, K=128)
    {
        dim3 grid((NN + 63) / 64, D_HID / 64);
        k_gemm<<<grid, 256>>>(x, W1, nullptr, p_xw1, NN, D_HID, D_IN, 0);
    }
    // agg1[col] += xw1[row] * norm
    k_scatter1<<<(int)((E + 7) / 8), 256>>>(ei, E);

    // xw2 = relu(agg1 + b1) @ W2    (M=NN, N=64, K=128)
    {
        dim3 grid((NN + 63) / 64, D_OUT / 64);
        k_gemm<<<grid, 256>>>(p_agg1, W2, b1, p_xw2, NN, D_OUT, D_HID, 1);
    }
    // agg2[col] += xw2[row] * norm
    k_scatter2<<<(int)((E + 15) / 16), 256>>>(ei, E);

    // edge scores
    k_score<<<(int)((E + 7) / 8), 256>>>(ei, E, b2, out);
}

// round 4
// speedup vs baseline: 1.4053x; 1.4053x over previous
#include <cuda_runtime.h>

#define NN 100000
#define D_IN 128
#define D_HID 128
#define D_OUT 64
#define EMAX 1600000
#define NBLK 391   // ceil(NN/256)

// ---------------- scratch (device globals; no allocation allowed) ----------------
__device__ int   g_cnt[NN];                      // in-degree histogram (by col)
__device__ int   g_off[NN + 1];                  // CSR offsets
__device__ int   g_cur[NN];                      // bin cursors
__device__ int   g_bsum[512];                    // scan block sums
__device__ int   g_src[EMAX];                    // source node per sorted edge slot
__device__ float g_dinv[NN];
__device__ float g_xw1[(long long)NN * D_HID];   // x @ W1
__device__ float g_agg1[(long long)NN * D_HID];  // layer-1 aggregation
__device__ float g_xw2[(long long)NN * D_OUT];   // relu(agg1+b1) @ W2
__device__ float g_h2[(long long)NN * D_OUT];    // layer-2 aggregation + b2
__device__ int   g_idx64;

__device__ __forceinline__ long long ld_idx(const void* p, long long i, int is64) {
    if (is64) return ((const long long*)p)[i];
    return (long long)((const int*)p)[i];
}

// ---------------- zero histogram + sniff index dtype ----------------
__global__ void k_zero(const void* ei) {
    int i = blockIdx.x * blockDim.x + threadIdx.x;
    if (i < NN) g_cnt[i] = 0;
    if (blockIdx.x == 0 && threadIdx.x == 0) {
        // int64 nonneg < 2^31 => every odd 32-bit word is 0; for int32 those
        // words are random ids (P[all 16 zero] ~ 0). Reads stay in-bounds.
        const unsigned* w = (const unsigned*)ei;
        int all0 = 1;
        for (int k = 1; k < 32; k += 2) all0 &= (w[k] == 0u);
        g_idx64 = all0;
    }
}

// ---------------- in-degree histogram ----------------
__global__ void k_deg(const void* ei, long long E) {
    int is64 = g_idx64;
    long long e = (long long)blockIdx.x * blockDim.x + threadIdx.x;
    if (e >= E) return;
    int c = (int)ld_idx(ei, E + e, is64);
    atomicAdd(&g_cnt[c], 1);
}

// ---------------- 3-step exclusive scan of g_cnt -> g_off ----------------
__global__ void k_scan_blk() {
    __shared__ int s[256];
    int t = threadIdx.x;
    int idx = blockIdx.x * 256 + t;
    int v = (idx < NN) ? g_cnt[idx] : 0;
    s[t] = v;
    __syncthreads();
    #pragma unroll
    for (int o = 1; o < 256; o <<= 1) {
        int x = (t >= o) ? s[t - o] : 0;
        __syncthreads();
        s[t] += x;
        __syncthreads();
    }
    if (idx < NN) g_off[idx] = s[t] - v;   // exclusive within block
    if (t == 255) g_bsum[blockIdx.x] = s[255];
}

__global__ void k_scan_top() {
    __shared__ int s[512];
    int t = threadIdx.x;
    int v = (t < NBLK) ? g_bsum[t] : 0;
    s[t] = v;
    __syncthreads();
    #pragma unroll
    for (int o = 1; o < 512; o <<= 1) {
        int x = (t >= o) ? s[t - o] : 0;
        __syncthreads();
        s[t] += x;
        __syncthreads();
    }
    if (t < NBLK) g_bsum[t] = s[t] - v;    // exclusive
}

__global__ void k_scan_add(long long E) {
    int idx = blockIdx.x * blockDim.x + threadIdx.x;
    if (idx < NN) {
        int off = g_off[idx] + g_bsum[idx >> 8];
        g_off[idx] = off;
        g_cur[idx] = off;
        int c = g_cnt[idx];
        g_dinv[idx] = (c > 0) ? rsqrtf((float)c) : 0.0f;
    }
    if (idx == 0) g_off[NN] = (int)E;
}

// ---------------- counting-sort edges by target node ----------------
__global__ void k_binsort(const void* ei, long long E) {
    int is64 = g_idx64;
    long long e = (long long)blockIdx.x * blockDim.x + threadIdx.x;
    if (e >= E) return;
    int r = (int)ld_idx(ei, e, is64);
    int c = (int)ld_idx(ei, E + e, is64);
    int pos = atomicAdd(&g_cur[c], 1);
    g_src[pos] = r;
}

// ---------------- SGEMM: C = op(A) @ B, BM=128, BK=8, TM=8 ----------------
// op(A) = relu(A + bias) if RELU (bias indexed by K), else A. 256 threads.
template<int BN, int TN, bool RELU>
__global__ __launch_bounds__(256) void k_gemm(
    const float* __restrict__ A, const float* __restrict__ B,
    const float* __restrict__ bias, float* __restrict__ C,
    int M, int N, int K)
{
    __shared__ float As[8][132];   // [k][m], padded (132*4B = 16B-aligned rows)
    __shared__ float Bs[8][BN];    // [k][n]

    const int tid = threadIdx.x;
    const int tx = tid & 15;                 // 16 col groups
    const int ty = tid >> 4;                 // 16 row groups
    const int m0 = blockIdx.x * 128;
    const int n0 = blockIdx.y * BN;

    const int arow = tid >> 1;               // 0..127
    const int ak   = (tid & 1) * 4;          // 0 or 4
    const int b4   = BN / 4;
    const int brow = tid / b4;
    const int bcol = (tid % b4) * 4;
    const bool bact = tid < 8 * b4;

    float acc[8][TN] = {};

    for (int kt = 0; kt < K; kt += 8) {
        // A tile -> As (transposed)
        {
            float4 av = make_float4(0.f, 0.f, 0.f, 0.f);
            int gm = m0 + arow;
            if (gm < M) {
                av = *(const float4*)(A + (long long)gm * K + kt + ak);
                if (RELU) {
                    const float* bp = bias + kt + ak;
                    av.x = fmaxf(av.x + bp[0], 0.f);
                    av.y = fmaxf(av.y + bp[1], 0.f);
                    av.z = fmaxf(av.z + bp[2], 0.f);
                    av.w = fmaxf(av.w + bp[3], 0.f);
                }
            }
            As[ak + 0][arow] = av.x;
            As[ak + 1][arow] = av.y;
            As[ak + 2][arow] = av.z;
            As[ak + 3][arow] = av.w;
        }
        // B tile
        if (bact)
            *(float4*)&Bs[brow][bcol] = *(const float4*)(B + (long long)(kt + brow) * N + n0 + bcol);
        __syncthreads();

        #pragma unroll
        for (int kk = 0; kk < 8; kk++) {
            float a[8], b[TN];
            *(float4*)&a[0] = *(const float4*)&As[kk][ty * 8];
            *(float4*)&a[4] = *(const float4*)&As[kk][ty * 8 + 4];
            #pragma unroll
            for (int j = 0; j < TN; j += 4)
                *(float4*)&b[j] = *(const float4*)&Bs[kk][tx * TN + j];
            #pragma unroll
            for (int i = 0; i < 8; i++)
                #pragma unroll
                for (int j = 0; j < TN; j++)
                    acc[i][j] += a[i] * b[j];
        }
        __syncthreads();
    }

    #pragma unroll
    for (int i = 0; i < 8; i++) {
        int gm = m0 + ty * 8 + i;
        if (gm < M) {
            #pragma unroll
            for (int j = 0; j < TN; j += 4)
                *(float4*)(C + (long long)gm * N + n0 + tx * TN + j) =
                    make_float4(acc[i][j], acc[i][j+1], acc[i][j+2], acc[i][j+3]);
        }
    }
}

// ---------------- layer-1 aggregation: warp per node, 128 floats ----------------
__global__ void k_agg1() {
    int n = blockIdx.x * 8 + (threadIdx.x >> 5);
    if (n >= NN) return;
    int lane = threadIdx.x & 31;
    int j = g_off[n], j1 = g_off[n + 1];
    float dc = g_dinv[n];
    float4 acc = make_float4(0.f, 0.f, 0.f, 0.f);
    for (; j + 1 < j1; j += 2) {
        int r0 = g_src[j], r1 = g_src[j + 1];
        float n0 = dc * g_dinv[r0];
        float n1 = dc * g_dinv[r1];
        float4 v0 = *((const float4*)(g_xw1 + (long long)r0 * D_HID) + lane);
        float4 v1 = *((const float4*)(g_xw1 + (long long)r1 * D_HID) + lane);
        acc.x += v0.x * n0 + v1.x * n1;
        acc.y += v0.y * n0 + v1.y * n1;
        acc.z += v0.z * n0 + v1.z * n1;
        acc.w += v0.w * n0 + v1.w * n1;
    }
    if (j < j1) {
        int r = g_src[j];
        float nr = dc * g_dinv[r];
        float4 v = *((const float4*)(g_xw1 + (long long)r * D_HID) + lane);
        acc.x += v.x * nr; acc.y += v.y * nr; acc.z += v.z * nr; acc.w += v.w * nr;
    }
    *((float4*)(g_agg1 + (long long)n * D_HID) + lane) = acc;
}

// ---------------- layer-2 aggregation (+b2): warp per node, 64 floats ----------------
__global__ void k_agg2(const float* __restrict__ b2) {
    int n = blockIdx.x * 8 + (threadIdx.x >> 5);
    if (n >= NN) return;
    int lane = threadIdx.x & 31;
    int j = g_off[n], j1 = g_off[n + 1];
    float dc = g_dinv[n];
    float2 acc = make_float2(0.f, 0.f);
    for (; j + 1 < j1; j += 2) {
        int r0 = g_src[j], r1 = g_src[j + 1];
        float n0 = dc * g_dinv[r0];
        float n1 = dc * g_dinv[r1];
        float2 v0 = *((const float2*)(g_xw2 + (long long)r0 * D_OUT) + lane);
        float2 v1 = *((const float2*)(g_xw2 + (long long)r1 * D_OUT) + lane);
        acc.x += v0.x * n0 + v1.x * n1;
        acc.y += v0.y * n0 + v1.y * n1;
    }
    if (j < j1) {
        int r = g_src[j];
        float nr = dc * g_dinv[r];
        float2 v = *((const float2*)(g_xw2 + (long long)r * D_OUT) + lane);
        acc.x += v.x * nr; acc.y += v.y * nr;
    }
    float2 bv = *((const float2*)b2 + lane);
    *((float2*)(g_h2 + (long long)n * D_OUT) + lane) =
        make_float2(acc.x + bv.x, acc.y + bv.y);
}

// ---------------- edge score = sigmoid(dot(h2[row], h2[col])) ----------------
__global__ void k_score(const void* ei, long long E, float* __restrict__ out) {
    int is64 = g_idx64;
    long long warp = (long long)blockIdx.x * 8 + (threadIdx.x >> 5);
    int lane = threadIdx.x & 31;
    if (warp >= E) return;
    long long r = ld_idx(ei, warp, is64);
    long long c = ld_idx(ei, E + warp, is64);
    float2 hr = *((const float2*)(g_h2 + r * D_OUT) + lane);
    float2 hc = *((const float2*)(g_h2 + c * D_OUT) + lane);
    float s = hr.x * hc.x + hr.y * hc.y;
    #pragma unroll
    for (int o = 16; o > 0; o >>= 1) s += __shfl_xor_sync(0xFFFFFFFF, s, o);
    if (lane == 0) out[warp] = 1.0f / (1.0f + __expf(-s));
}

// ---------------- launch ----------------
extern "C" void kernel_launch(void* const* d_in, const int* in_sizes, int n_in,
                              void* d_out, int out_size) {
    const float* x  = (const float*)d_in[0];
    const void*  ei = d_in[1];
    const float* W1 = (const float*)d_in[2];
    const float* b1 = (const float*)d_in[3];
    const float* W2 = (const float*)d_in[4];
    const float* b2 = (const float*)d_in[5];
    float* out = (float*)d_out;
    long long E = (long long)in_sizes[1] / 2;

    float *p_xw1, *p_agg1, *p_xw2;
    cudaGetSymbolAddress((void**)&p_xw1,  g_xw1);
    cudaGetSymbolAddress((void**)&p_agg1, g_agg1);
    cudaGetSymbolAddress((void**)&p_xw2,  g_xw2);

    int eblk = (int)((E + 255) / 256);

    k_zero<<<NBLK, 256>>>(ei);
    k_deg<<<eblk, 256>>>(ei, E);
    k_scan_blk<<<NBLK, 256>>>();
    k_scan_top<<<1, 512>>>();
    k_scan_add<<<NBLK, 256>>>(E);
    k_binsort<<<eblk, 256>>>(ei, E);

    // xw1 = x @ W1  (M=NN, N=128, K=128)
    k_gemm<128, 8, false><<<dim3((NN + 127) / 128, 1), 256>>>(x, W1, nullptr, p_xw1, NN, D_HID, D_IN);
    // agg1[n] = sum_{e: col=n} norm * xw1[row]
    k_agg1<<<(NN + 7) / 8, 256>>>();
    // xw2 = relu(agg1 + b1) @ W2  (M=NN, N=64, K=128)
    k_gemm<64, 4, true><<<dim3((NN + 127) / 128, 1), 256>>>(p_agg1, W2, b1, p_xw2, NN, D_OUT, D_HID);
    // h2[n] = sum norm * xw2[row] + b2
    k_agg2<<<(NN + 7) / 8, 256>>>(b2);
    // edge scores
    k_score<<<(int)((E + 7) / 8), 256>>>(ei, E, out);
}